// round 13
// baseline (speedup 1.0000x reference)
#include <cuda_runtime.h>
#include <math.h>

#define Bb 8
#define Nn 4096
#define Dd 128
#define Kk 256
#define NT 32            // N / 128 tile blocks
#define NTILES 528       // NT*(NT+1)/2 upper-triangle 128x128 tiles

// ---- output layout (flattened tuple, float32) ----
#define OFF_S    0
#define OFF_FC   32768
#define OFF_FCM  294912
#define OFF_FNCM 295936

// ---- scratch (device globals: allocation-free per harness rules) ----
__device__ float  g_A[134217728];          // 8*4096*4096; only upper tiles used
__device__ float  g_Xc[4194304];           // centered X
__device__ double g_meanpart[Bb][32][Dd];  // per-chunk column sums (double)
__device__ float  g_mean[Bb * Dd];
__device__ float  g_colsum[Bb * Dd];
__device__ float  g_r[Bb * Nn];            // 1/var per row
__device__ float  g_y[Bb * Nn];            // X @ W^T
__device__ float  g_rowpart[Bb][NT][Nn];   // rowsum partials (unique slots)
__device__ float  g_ypart[Bb][NT][Nn];     // matvec partials (unique slots)
__device__ float  g_dvec[Bb * Nn];         // rowsum^-0.5
__device__ float  g_w[Bb * Nn];            // d * y
__device__ int    g_idx[Bb * Kk];          // top-k indices

// ------------------------------------------------------------------
__global__ void k_meanpart(const float* __restrict__ X) {
    int b = blockIdx.y, c = blockIdx.x, d = threadIdx.x;
    const float* p = X + ((size_t)b * Nn + (size_t)c * 128) * Dd + d;
    double s = 0.0;
#pragma unroll 4
    for (int n = 0; n < 128; ++n) s += (double)p[(size_t)n * Dd];
    g_meanpart[b][c][d] = s;
}

__global__ void k_meanred() {
    int i = blockIdx.x * 256 + threadIdx.x;   // 1024 = B*D
    if (i >= Bb * Dd) return;
    int b = i >> 7, d = i & 127;
    double s = 0.0;
    for (int c = 0; c < 32; ++c) s += g_meanpart[b][c][d];
    g_colsum[i] = (float)s;
    g_mean[i]   = (float)(s / (double)Nn);
}

// ------------------------------------------------------------------
// per-row: xc, r = 1/(sqrtf(sum xc^2)+1e-6), y = x.W
__global__ void k_vary(const float* __restrict__ X, const float* __restrict__ W) {
    int rowg = blockIdx.x;            // b*N + n
    int b = rowg >> 12;
    int d = threadIdx.x;

    float x  = X[(size_t)rowg * Dd + d];
    float m  = g_mean[b * Dd + d];
    float xc = x - m;
    double ss = (double)xc * (double)xc;
    double yv = (double)x * (double)W[d];

    for (int o = 16; o; o >>= 1) {
        ss += __shfl_down_sync(0xFFFFFFFFu, ss, o);
        yv += __shfl_down_sync(0xFFFFFFFFu, yv, o);
    }
    __shared__ double sss[4], syv[4];
    int wid = threadIdx.x >> 5, lane = threadIdx.x & 31;
    if (lane == 0) { sss[wid] = ss; syv[wid] = yv; }
    __syncthreads();

    g_Xc[(size_t)rowg * Dd + d] = xc;
    if (d == 0) {
        float ssT = (float)(sss[0] + sss[1] + sss[2] + sss[3]);
        float var = sqrtf(ssT) + 1e-6f;
        g_r[rowg] = 1.0f / var;
        g_y[rowg] = (float)(syv[0] + syv[1] + syv[2] + syv[3]);
    }
}

// ------------------------------------------------------------------
__device__ __forceinline__ void tile_map(int p, int& ti, int& tj) {
    ti = 0;
    while (p >= NT - ti) { p -= NT - ti; ++ti; }
    tj = ti + p;
}

// ------------------------------------------------------------------
// Phase 1: 128x128 upper tiles of A = |cov * r_i * r_j|.
// 256 threads, 8x8 register tile, BK=16, double-buffered smem with
// register-staged global prefetch (one barrier per k-chunk).
__global__ void __launch_bounds__(256, 2) k_corr() {
    __shared__ float sa[2][16][128];
    __shared__ float sb[2][16][128];
    __shared__ float rrow[128], rcol[128];
    __shared__ float rs[128];

    int b = blockIdx.y;
    int ti, tj;
    tile_map(blockIdx.x, ti, tj);
    int bRow = ti * 128, bCol = tj * 128;

    const float* Xb = g_Xc + (size_t)b * Nn * Dd;
    int t = threadIdx.x;
    int tx = t & 15, ty = t >> 4;

    if (t < 128) rrow[t] = g_r[b * Nn + bRow + t];
    else         rcol[t - 128] = g_r[b * Nn + bCol + (t - 128)];

    float acc[8][8];
#pragma unroll
    for (int i = 0; i < 8; ++i)
#pragma unroll
        for (int j = 0; j < 8; ++j) acc[i][j] = 0.f;

    int mload = t >> 2;            // 0..63
    int kq = (t & 3) << 2;         // 0,4,8,12

    const float* pa0 = Xb + (size_t)(bRow + mload) * Dd + kq;
    const float* pa1 = Xb + (size_t)(bRow + mload + 64) * Dd + kq;
    const float* pb0 = Xb + (size_t)(bCol + mload) * Dd + kq;
    const float* pb1 = Xb + (size_t)(bCol + mload + 64) * Dd + kq;

    // prefetch kc=0
    float4 va0 = *(const float4*)(pa0);
    float4 va1 = *(const float4*)(pa1);
    float4 vb0 = *(const float4*)(pb0);
    float4 vb1 = *(const float4*)(pb1);

    int p = 0;
    // store buf 0
    sa[0][kq + 0][mload] = va0.x; sa[0][kq + 1][mload] = va0.y;
    sa[0][kq + 2][mload] = va0.z; sa[0][kq + 3][mload] = va0.w;
    sa[0][kq + 0][mload + 64] = va1.x; sa[0][kq + 1][mload + 64] = va1.y;
    sa[0][kq + 2][mload + 64] = va1.z; sa[0][kq + 3][mload + 64] = va1.w;
    sb[0][kq + 0][mload] = vb0.x; sb[0][kq + 1][mload] = vb0.y;
    sb[0][kq + 2][mload] = vb0.z; sb[0][kq + 3][mload] = vb0.w;
    sb[0][kq + 0][mload + 64] = vb1.x; sb[0][kq + 1][mload + 64] = vb1.y;
    sb[0][kq + 2][mload + 64] = vb1.z; sb[0][kq + 3][mload + 64] = vb1.w;
    __syncthreads();

#pragma unroll 1
    for (int kc = 16; kc < 128; kc += 16) {
        // issue global prefetch for this kc (lands during compute below)
        va0 = *(const float4*)(pa0 + kc);
        va1 = *(const float4*)(pa1 + kc);
        vb0 = *(const float4*)(pb0 + kc);
        vb1 = *(const float4*)(pb1 + kc);

#pragma unroll
        for (int k = 0; k < 16; ++k) {
            float af[8], bf[8];
            *(float4*)&af[0] = *(const float4*)&sa[p][k][ty * 4];
            *(float4*)&af[4] = *(const float4*)&sa[p][k][64 + ty * 4];
            *(float4*)&bf[0] = *(const float4*)&sb[p][k][tx * 4];
            *(float4*)&bf[4] = *(const float4*)&sb[p][k][64 + tx * 4];
#pragma unroll
            for (int i = 0; i < 8; ++i)
#pragma unroll
                for (int j = 0; j < 8; ++j)
                    acc[i][j] += af[i] * bf[j];
        }

        int q = p ^ 1;
        sa[q][kq + 0][mload] = va0.x; sa[q][kq + 1][mload] = va0.y;
        sa[q][kq + 2][mload] = va0.z; sa[q][kq + 3][mload] = va0.w;
        sa[q][kq + 0][mload + 64] = va1.x; sa[q][kq + 1][mload + 64] = va1.y;
        sa[q][kq + 2][mload + 64] = va1.z; sa[q][kq + 3][mload + 64] = va1.w;
        sb[q][kq + 0][mload] = vb0.x; sb[q][kq + 1][mload] = vb0.y;
        sb[q][kq + 2][mload] = vb0.z; sb[q][kq + 3][mload] = vb0.w;
        sb[q][kq + 0][mload + 64] = vb1.x; sb[q][kq + 1][mload + 64] = vb1.y;
        sb[q][kq + 2][mload + 64] = vb1.z; sb[q][kq + 3][mload + 64] = vb1.w;
        __syncthreads();
        p = q;
    }

    // final k-chunk
#pragma unroll
    for (int k = 0; k < 16; ++k) {
        float af[8], bf[8];
        *(float4*)&af[0] = *(const float4*)&sa[p][k][ty * 4];
        *(float4*)&af[4] = *(const float4*)&sa[p][k][64 + ty * 4];
        *(float4*)&bf[0] = *(const float4*)&sb[p][k][tx * 4];
        *(float4*)&bf[4] = *(const float4*)&sb[p][k][64 + tx * 4];
#pragma unroll
        for (int i = 0; i < 8; ++i)
#pragma unroll
            for (int j = 0; j < 8; ++j)
                acc[i][j] += af[i] * bf[j];
    }

    // epilogue: scale + abs in place
    float rr_[8], rc_[8];
#pragma unroll
    for (int i = 0; i < 8; ++i) {
        int r = (i < 4) ? (ty * 4 + i) : (64 + ty * 4 + i - 4);
        rr_[i] = rrow[r];
    }
#pragma unroll
    for (int j = 0; j < 8; ++j) {
        int c = (j < 4) ? (tx * 4 + j) : (64 + tx * 4 + j - 4);
        rc_[j] = rcol[c];
    }
#pragma unroll
    for (int i = 0; i < 8; ++i)
#pragma unroll
        for (int j = 0; j < 8; ++j)
            acc[i][j] = fabsf(acc[i][j] * rr_[i] * rc_[j]);

    // straight tile write (float4, coalesced)
    float* Ab = g_A + (size_t)b * Nn * Nn;
#pragma unroll
    for (int i = 0; i < 8; ++i) {
        int r = (i < 4) ? (ty * 4 + i) : (64 + ty * 4 + i - 4);
        float4 w0 = make_float4(acc[i][0], acc[i][1], acc[i][2], acc[i][3]);
        float4 w1 = make_float4(acc[i][4], acc[i][5], acc[i][6], acc[i][7]);
        *(float4*)(Ab + (size_t)(bRow + r) * Nn + bCol + tx * 4)      = w0;
        *(float4*)(Ab + (size_t)(bRow + r) * Nn + bCol + 64 + tx * 4) = w1;
    }

    // row sums: per-thread sum of 8 cols, xor-shuffle over the 16 tx lanes
#pragma unroll
    for (int i = 0; i < 8; ++i) {
        float lr = 0.f;
#pragma unroll
        for (int j = 0; j < 8; ++j) lr += acc[i][j];
        for (int o = 8; o; o >>= 1) lr += __shfl_xor_sync(0xFFFFFFFFu, lr, o, 16);
        if (tx == 0) {
            int r = (i < 4) ? (ty * 4 + i) : (64 + ty * 4 + i - 4);
            rs[r] = lr;
        }
    }

    // col partial sums: reuse sa[0] as [16][128] scratch (dead now)
    __syncthreads();
#pragma unroll
    for (int j = 0; j < 8; ++j) {
        float lc = 0.f;
#pragma unroll
        for (int i = 0; i < 8; ++i) lc += acc[i][j];
        int c = (j < 4) ? (tx * 4 + j) : (64 + tx * 4 + j - 4);
        sa[0][ty][c] = lc;
    }
    __syncthreads();

    if (t < 128) {
        g_rowpart[b][tj][bRow + t] = rs[t];
        if (ti != tj) {
            float s = 0.f;
#pragma unroll
            for (int q = 0; q < 16; ++q) s += sa[0][q][t];
            g_rowpart[b][ti][bCol + t] = s;
        }
    }
}

// ------------------------------------------------------------------
// rowsum reduce (Kahan) ; d = rowsum^-0.5 ; w = d*y
__global__ void k_rowred() {
    int i = blockIdx.x * 256 + threadIdx.x;   // B*N = 32768
    int b = i >> 12, n = i & 4095;
    float s = 0.f, c = 0.f;
#pragma unroll
    for (int j = 0; j < NT; ++j) {
        float yk = g_rowpart[b][j][n] - c;
        float tt = s + yk;
        c = (tt - s) - yk;
        s = tt;
    }
    float dv = 1.0f / sqrtf(s);
    g_dvec[i] = dv;
    g_w[i] = dv * g_y[i];
}

// ------------------------------------------------------------------
// Phase 2: symmetric tile matvec, register-resident single pass.
// 8 warps x 16 rows each; one coalesced float4 read per lane feeds
// both the row dot (u) and the column accumulator (v).
// grid (528, B), 256 threads.
__global__ void __launch_bounds__(256) k_spmv() {
    __shared__ float wr[128], wc[128];
    __shared__ float usum[128];
    __shared__ float vpart[8][128];

    int b = blockIdx.y;
    int ti, tj;
    tile_map(blockIdx.x, ti, tj);
    int bRow = ti * 128, bCol = tj * 128;
    int t = threadIdx.x;
    int w = t >> 5, lane = t & 31;

    if (t < 128)      wr[t] = g_w[b * Nn + bRow + t];
    else              wc[t - 128] = g_w[b * Nn + bCol + (t - 128)];
    __syncthreads();

    const float* Ab = g_A + (size_t)b * Nn * Nn;
    float myc0 = wc[lane * 4 + 0], myc1 = wc[lane * 4 + 1];
    float myc2 = wc[lane * 4 + 2], myc3 = wc[lane * 4 + 3];

    float v0 = 0.f, v1 = 0.f, v2 = 0.f, v3 = 0.f;

#pragma unroll 4
    for (int rr = 0; rr < 16; ++rr) {
        int r = w * 16 + rr;
        float4 a = *(const float4*)(Ab + (size_t)(bRow + r) * Nn + bCol + lane * 4);
        // u: row dot
        float u = a.x * myc0 + a.y * myc1 + a.z * myc2 + a.w * myc3;
        for (int o = 16; o; o >>= 1) u += __shfl_xor_sync(0xFFFFFFFFu, u, o);
        if (lane == 0) usum[r] = u;
        // v: column accumulation (fixed order over rr)
        float wrv = wr[r];
        v0 += a.x * wrv; v1 += a.y * wrv; v2 += a.z * wrv; v3 += a.w * wrv;
    }
    vpart[w][lane * 4 + 0] = v0;
    vpart[w][lane * 4 + 1] = v1;
    vpart[w][lane * 4 + 2] = v2;
    vpart[w][lane * 4 + 3] = v3;
    __syncthreads();

    if (t < 128) {
        g_ypart[b][tj][bRow + t] = usum[t];
        if (ti != tj) {
            float s = 0.f;
#pragma unroll
            for (int q = 0; q < 8; ++q) s += vpart[q][t];
            g_ypart[b][ti][bCol + t] = s;
        }
    }
}

// ------------------------------------------------------------------
// S = d * (sum of 32 matvec partials)  (Kahan)
__global__ void k_sred(float* __restrict__ out) {
    int i = blockIdx.x * 256 + threadIdx.x;   // 32768
    int b = i >> 12, n = i & 4095;
    float s = 0.f, c = 0.f;
#pragma unroll
    for (int j = 0; j < NT; ++j) {
        float yk = g_ypart[b][j][n] - c;
        float tt = s + yk;
        c = (tt - s) - yk;
        s = tt;
    }
    out[OFF_S + i] = g_dvec[i] * (s + c);
}

// ------------------------------------------------------------------
// top-K via bitonic sort: descending score, ascending index on ties.
__global__ void k_topk(const float* __restrict__ S) {
    __shared__ unsigned long long key[4096];
    int b = blockIdx.x;
    for (int i = threadIdx.x; i < 4096; i += 1024) {
        unsigned u  = __float_as_uint(S[OFF_S + b * Nn + i]);
        unsigned up = (u & 0x80000000u) ? ~u : (u | 0x80000000u);
        unsigned kd = ~up;
        key[i] = ((unsigned long long)kd << 32) | (unsigned)i;
    }
    __syncthreads();
    for (int size = 2; size <= 4096; size <<= 1) {
        for (int stride = size >> 1; stride; stride >>= 1) {
#pragma unroll
            for (int q = 0; q < 2; ++q) {
                int t  = threadIdx.x + q * 1024;
                int lo = 2 * t - (t & (stride - 1));
                int hi = lo + stride;
                bool asc = (lo & size) == 0;
                unsigned long long a = key[lo], c = key[hi];
                if ((a > c) == asc) { key[lo] = c; key[hi] = a; }
            }
            __syncthreads();
        }
    }
    if (threadIdx.x < Kk)
        g_idx[b * Kk + threadIdx.x] = (int)(key[threadIdx.x] & 0xFFFFFFFFu);
}

// ------------------------------------------------------------------
// gather F_c, parallel over (b, k-chunk). grid (16, 8), 128 threads.
__global__ void k_gather(const float* __restrict__ X, float* __restrict__ out) {
    int b = blockIdx.y, kc = blockIdx.x, d = threadIdx.x;
#pragma unroll
    for (int q = 0; q < 16; ++q) {
        int k = kc * 16 + q;
        int n = g_idx[b * Kk + k];
        out[OFF_FC + ((size_t)b * Kk + k) * Dd + d] = X[((size_t)b * Nn + n) * Dd + d];
    }
}

// means: grid B, 128 threads (= d)
__global__ void k_means(const float* __restrict__ X, float* __restrict__ out) {
    int b = blockIdx.x, d = threadIdx.x;
    float s = 0.f;
#pragma unroll 4
    for (int k = 0; k < Kk; ++k) {
        int n = g_idx[b * Kk + k];
        s += X[((size_t)b * Nn + n) * Dd + d];
    }
    out[OFF_FCM  + b * Dd + d] = s * (1.f / (float)Kk);
    out[OFF_FNCM + b * Dd + d] = (g_colsum[b * Dd + d] - s) * (1.f / (float)(Nn - Kk));
}

// ------------------------------------------------------------------
extern "C" void kernel_launch(void* const* d_in, const int* in_sizes, int n_in,
                              void* d_out, int out_size) {
    const float* X = (const float*)d_in[0];   // [8,4096,128] f32
    const float* W = (const float*)d_in[1];   // [1,128] f32
    float* out = (float*)d_out;

    dim3 gmp(32, Bb);
    k_meanpart<<<gmp, 128>>>(X);
    k_meanred<<<4, 256>>>();

    k_vary<<<Bb * Nn, 128>>>(X, W);

    dim3 gc(NTILES, Bb);
    k_corr<<<gc, 256>>>();

    k_rowred<<<128, 256>>>();

    k_spmv<<<gc, 256>>>();

    k_sred<<<128, 256>>>(out);

    k_topk<<<Bb, 1024>>>(out);

    dim3 gg(16, Bb);
    k_gather<<<gg, 128>>>(X, out);
    k_means<<<Bb, 128>>>(X, out);
}

// round 17
// speedup vs baseline: 1.0029x; 1.0029x over previous
#include <cuda_runtime.h>
#include <math.h>
#include <stdint.h>

#define Bb 8
#define Nn 4096
#define Dd 128
#define Kk 256
#define NT 32            // N / 128 tile blocks
#define NTILES 528       // NT*(NT+1)/2 upper-triangle 128x128 tiles

// ---- output layout (flattened tuple, float32) ----
#define OFF_S    0
#define OFF_FC   32768
#define OFF_FCM  294912
#define OFF_FNCM 295936

// ---- scratch (device globals: allocation-free per harness rules) ----
__device__ float  g_A[134217728];          // 8*4096*4096; only upper tiles used
__device__ float  g_Xc[4194304];           // centered X
__device__ double g_meanpart[Bb][32][Dd];  // per-chunk column sums (double)
__device__ float  g_mean[Bb * Dd];
__device__ float  g_colsum[Bb * Dd];
__device__ float  g_r[Bb * Nn];            // 1/var per row
__device__ float  g_y[Bb * Nn];            // X @ W^T
__device__ float  g_rowpart[Bb][NT][Nn];   // rowsum partials (unique slots)
__device__ float  g_ypart[Bb][NT][Nn];     // matvec partials (unique slots)
__device__ float  g_dvec[Bb * Nn];         // rowsum^-0.5
__device__ float  g_w[Bb * Nn];            // d * y
__device__ int    g_idx[Bb * Kk];          // top-k indices

// ------------------------------------------------------------------
__global__ void k_meanpart(const float* __restrict__ X) {
    int b = blockIdx.y, c = blockIdx.x, d = threadIdx.x;
    const float* p = X + ((size_t)b * Nn + (size_t)c * 128) * Dd + d;
    double s = 0.0;
#pragma unroll 4
    for (int n = 0; n < 128; ++n) s += (double)p[(size_t)n * Dd];
    g_meanpart[b][c][d] = s;
}

__global__ void k_meanred() {
    int i = blockIdx.x * 256 + threadIdx.x;   // 1024 = B*D
    if (i >= Bb * Dd) return;
    int b = i >> 7, d = i & 127;
    double s = 0.0;
    for (int c = 0; c < 32; ++c) s += g_meanpart[b][c][d];
    g_colsum[i] = (float)s;
    g_mean[i]   = (float)(s / (double)Nn);
}

// ------------------------------------------------------------------
// per-row: xc, r = 1/(sqrtf(sum xc^2)+1e-6), y = x.W
__global__ void k_vary(const float* __restrict__ X, const float* __restrict__ W) {
    int rowg = blockIdx.x;            // b*N + n
    int b = rowg >> 12;
    int d = threadIdx.x;

    float x  = X[(size_t)rowg * Dd + d];
    float m  = g_mean[b * Dd + d];
    float xc = x - m;
    double ss = (double)xc * (double)xc;
    double yv = (double)x * (double)W[d];

    for (int o = 16; o; o >>= 1) {
        ss += __shfl_down_sync(0xFFFFFFFFu, ss, o);
        yv += __shfl_down_sync(0xFFFFFFFFu, yv, o);
    }
    __shared__ double sss[4], syv[4];
    int wid = threadIdx.x >> 5, lane = threadIdx.x & 31;
    if (lane == 0) { sss[wid] = ss; syv[wid] = yv; }
    __syncthreads();

    g_Xc[(size_t)rowg * Dd + d] = xc;
    if (d == 0) {
        float ssT = (float)(sss[0] + sss[1] + sss[2] + sss[3]);
        float var = sqrtf(ssT) + 1e-6f;
        g_r[rowg] = 1.0f / var;
        g_y[rowg] = (float)(syv[0] + syv[1] + syv[2] + syv[3]);
    }
}

// ------------------------------------------------------------------
__device__ __forceinline__ void tile_map(int p, int& ti, int& tj) {
    ti = 0;
    while (p >= NT - ti) { p -= NT - ti; ++ti; }
    tj = ti + p;
}

// ------------------------------------------------------------------
// Phase 1 (UNCHANGED from the 672.5us passing kernel):
// 128x128 upper tiles of A = |cov * r_i * r_j|, 8x8 register tile,
// BK=16, double-buffered smem with register-staged global prefetch.
__global__ void __launch_bounds__(256, 2) k_corr() {
    __shared__ float sa[2][16][128];
    __shared__ float sb[2][16][128];
    __shared__ float rrow[128], rcol[128];
    __shared__ float rs[128];

    int b = blockIdx.y;
    int ti, tj;
    tile_map(blockIdx.x, ti, tj);
    int bRow = ti * 128, bCol = tj * 128;

    const float* Xb = g_Xc + (size_t)b * Nn * Dd;
    int t = threadIdx.x;
    int tx = t & 15, ty = t >> 4;

    if (t < 128) rrow[t] = g_r[b * Nn + bRow + t];
    else         rcol[t - 128] = g_r[b * Nn + bCol + (t - 128)];

    float acc[8][8];
#pragma unroll
    for (int i = 0; i < 8; ++i)
#pragma unroll
        for (int j = 0; j < 8; ++j) acc[i][j] = 0.f;

    int mload = t >> 2;            // 0..63
    int kq = (t & 3) << 2;         // 0,4,8,12

    const float* pa0 = Xb + (size_t)(bRow + mload) * Dd + kq;
    const float* pa1 = Xb + (size_t)(bRow + mload + 64) * Dd + kq;
    const float* pb0 = Xb + (size_t)(bCol + mload) * Dd + kq;
    const float* pb1 = Xb + (size_t)(bCol + mload + 64) * Dd + kq;

    float4 va0 = *(const float4*)(pa0);
    float4 va1 = *(const float4*)(pa1);
    float4 vb0 = *(const float4*)(pb0);
    float4 vb1 = *(const float4*)(pb1);

    int p = 0;
    sa[0][kq + 0][mload] = va0.x; sa[0][kq + 1][mload] = va0.y;
    sa[0][kq + 2][mload] = va0.z; sa[0][kq + 3][mload] = va0.w;
    sa[0][kq + 0][mload + 64] = va1.x; sa[0][kq + 1][mload + 64] = va1.y;
    sa[0][kq + 2][mload + 64] = va1.z; sa[0][kq + 3][mload + 64] = va1.w;
    sb[0][kq + 0][mload] = vb0.x; sb[0][kq + 1][mload] = vb0.y;
    sb[0][kq + 2][mload] = vb0.z; sb[0][kq + 3][mload] = vb0.w;
    sb[0][kq + 0][mload + 64] = vb1.x; sb[0][kq + 1][mload + 64] = vb1.y;
    sb[0][kq + 2][mload + 64] = vb1.z; sb[0][kq + 3][mload + 64] = vb1.w;
    __syncthreads();

#pragma unroll 1
    for (int kc = 16; kc < 128; kc += 16) {
        va0 = *(const float4*)(pa0 + kc);
        va1 = *(const float4*)(pa1 + kc);
        vb0 = *(const float4*)(pb0 + kc);
        vb1 = *(const float4*)(pb1 + kc);

#pragma unroll
        for (int k = 0; k < 16; ++k) {
            float af[8], bf[8];
            *(float4*)&af[0] = *(const float4*)&sa[p][k][ty * 4];
            *(float4*)&af[4] = *(const float4*)&sa[p][k][64 + ty * 4];
            *(float4*)&bf[0] = *(const float4*)&sb[p][k][tx * 4];
            *(float4*)&bf[4] = *(const float4*)&sb[p][k][64 + tx * 4];
#pragma unroll
            for (int i = 0; i < 8; ++i)
#pragma unroll
                for (int j = 0; j < 8; ++j)
                    acc[i][j] += af[i] * bf[j];
        }

        int q = p ^ 1;
        sa[q][kq + 0][mload] = va0.x; sa[q][kq + 1][mload] = va0.y;
        sa[q][kq + 2][mload] = va0.z; sa[q][kq + 3][mload] = va0.w;
        sa[q][kq + 0][mload + 64] = va1.x; sa[q][kq + 1][mload + 64] = va1.y;
        sa[q][kq + 2][mload + 64] = va1.z; sa[q][kq + 3][mload + 64] = va1.w;
        sb[q][kq + 0][mload] = vb0.x; sb[q][kq + 1][mload] = vb0.y;
        sb[q][kq + 2][mload] = vb0.z; sb[q][kq + 3][mload] = vb0.w;
        sb[q][kq + 0][mload + 64] = vb1.x; sb[q][kq + 1][mload + 64] = vb1.y;
        sb[q][kq + 2][mload + 64] = vb1.z; sb[q][kq + 3][mload + 64] = vb1.w;
        __syncthreads();
        p = q;
    }

#pragma unroll
    for (int k = 0; k < 16; ++k) {
        float af[8], bf[8];
        *(float4*)&af[0] = *(const float4*)&sa[p][k][ty * 4];
        *(float4*)&af[4] = *(const float4*)&sa[p][k][64 + ty * 4];
        *(float4*)&bf[0] = *(const float4*)&sb[p][k][tx * 4];
        *(float4*)&bf[4] = *(const float4*)&sb[p][k][64 + tx * 4];
#pragma unroll
        for (int i = 0; i < 8; ++i)
#pragma unroll
            for (int j = 0; j < 8; ++j)
                acc[i][j] += af[i] * bf[j];
    }

    float rr_[8], rc_[8];
#pragma unroll
    for (int i = 0; i < 8; ++i) {
        int r = (i < 4) ? (ty * 4 + i) : (64 + ty * 4 + i - 4);
        rr_[i] = rrow[r];
    }
#pragma unroll
    for (int j = 0; j < 8; ++j) {
        int c = (j < 4) ? (tx * 4 + j) : (64 + tx * 4 + j - 4);
        rc_[j] = rcol[c];
    }
#pragma unroll
    for (int i = 0; i < 8; ++i)
#pragma unroll
        for (int j = 0; j < 8; ++j)
            acc[i][j] = fabsf(acc[i][j] * rr_[i] * rc_[j]);

    float* Ab = g_A + (size_t)b * Nn * Nn;
#pragma unroll
    for (int i = 0; i < 8; ++i) {
        int r = (i < 4) ? (ty * 4 + i) : (64 + ty * 4 + i - 4);
        float4 w0 = make_float4(acc[i][0], acc[i][1], acc[i][2], acc[i][3]);
        float4 w1 = make_float4(acc[i][4], acc[i][5], acc[i][6], acc[i][7]);
        *(float4*)(Ab + (size_t)(bRow + r) * Nn + bCol + tx * 4)      = w0;
        *(float4*)(Ab + (size_t)(bRow + r) * Nn + bCol + 64 + tx * 4) = w1;
    }

#pragma unroll
    for (int i = 0; i < 8; ++i) {
        float lr = 0.f;
#pragma unroll
        for (int j = 0; j < 8; ++j) lr += acc[i][j];
        for (int o = 8; o; o >>= 1) lr += __shfl_xor_sync(0xFFFFFFFFu, lr, o, 16);
        if (tx == 0) {
            int r = (i < 4) ? (ty * 4 + i) : (64 + ty * 4 + i - 4);
            rs[r] = lr;
        }
    }

    __syncthreads();
#pragma unroll
    for (int j = 0; j < 8; ++j) {
        float lc = 0.f;
#pragma unroll
        for (int i = 0; i < 8; ++i) lc += acc[i][j];
        int c = (j < 4) ? (tx * 4 + j) : (64 + tx * 4 + j - 4);
        sa[0][ty][c] = lc;
    }
    __syncthreads();

    if (t < 128) {
        g_rowpart[b][tj][bRow + t] = rs[t];
        if (ti != tj) {
            float s = 0.f;
#pragma unroll
            for (int q = 0; q < 16; ++q) s += sa[0][q][t];
            g_rowpart[b][ti][bCol + t] = s;
        }
    }
}

// ------------------------------------------------------------------
// rowsum reduce (Kahan) ; d = rowsum^-0.5 ; w = d*y
__global__ void k_rowred() {
    int i = blockIdx.x * 256 + threadIdx.x;   // B*N = 32768
    int b = i >> 12, n = i & 4095;
    float s = 0.f, c = 0.f;
#pragma unroll
    for (int j = 0; j < NT; ++j) {
        float yk = g_rowpart[b][j][n] - c;
        float tt = s + yk;
        c = (tt - s) - yk;
        s = tt;
    }
    float dv = 1.0f / sqrtf(s);
    g_dvec[i] = dv;
    g_w[i] = dv * g_y[i];
}

// ------------------------------------------------------------------
// Phase 2: symmetric tile matvec. IDENTICAL arithmetic to the passing
// R13 kernel (same dot4, same 32-lane xor tree, same v order); only
// the 16 row loads are hoisted into registers first (MLP=16).
__global__ void __launch_bounds__(256) k_spmv() {
    __shared__ float wr[128], wc[128];
    __shared__ float usum[128];
    __shared__ float vpart[8][128];

    int b = blockIdx.y;
    int ti, tj;
    tile_map(blockIdx.x, ti, tj);
    int bRow = ti * 128, bCol = tj * 128;
    int t = threadIdx.x;
    int w = t >> 5, lane = t & 31;

    if (t < 128)      wr[t] = g_w[b * Nn + bRow + t];
    else              wc[t - 128] = g_w[b * Nn + bCol + (t - 128)];
    __syncthreads();

    const float* Ab = g_A + (size_t)b * Nn * Nn;
    float myc0 = wc[lane * 4 + 0], myc1 = wc[lane * 4 + 1];
    float myc2 = wc[lane * 4 + 2], myc3 = wc[lane * 4 + 3];

    // hoisted loads: all 16 rows in flight before any compute
    float4 a[16];
#pragma unroll
    for (int rr = 0; rr < 16; ++rr) {
        int r = w * 16 + rr;
        a[rr] = *(const float4*)(Ab + (size_t)(bRow + r) * Nn + bCol + lane * 4);
    }

    float v0 = 0.f, v1 = 0.f, v2 = 0.f, v3 = 0.f;
#pragma unroll
    for (int rr = 0; rr < 16; ++rr) {
        int r = w * 16 + rr;
        float u = a[rr].x * myc0 + a[rr].y * myc1 + a[rr].z * myc2 + a[rr].w * myc3;
        for (int o = 16; o; o >>= 1) u += __shfl_xor_sync(0xFFFFFFFFu, u, o);
        if (lane == 0) usum[r] = u;
        float wrv = wr[r];
        v0 += a[rr].x * wrv; v1 += a[rr].y * wrv; v2 += a[rr].z * wrv; v3 += a[rr].w * wrv;
    }
    vpart[w][lane * 4 + 0] = v0;
    vpart[w][lane * 4 + 1] = v1;
    vpart[w][lane * 4 + 2] = v2;
    vpart[w][lane * 4 + 3] = v3;
    __syncthreads();

    if (t < 128) {
        g_ypart[b][tj][bRow + t] = usum[t];
        if (ti != tj) {
            float s = 0.f;
#pragma unroll
            for (int q = 0; q < 8; ++q) s += vpart[q][t];
            g_ypart[b][ti][bCol + t] = s;
        }
    }
}

// ------------------------------------------------------------------
// Fused: S = d * (Kahan sum of 32 matvec partials) -- identical
// expression to R13's k_sred -- write S, then top-K bitonic sort
// (descending score, ascending index; matches lax.top_k).
__global__ void k_stopk(float* __restrict__ out) {
    __shared__ unsigned long long key[4096];
    int b = blockIdx.x;

#pragma unroll
    for (int q = 0; q < 4; ++q) {
        int n = threadIdx.x + q * 1024;
        float s = 0.f, c = 0.f;
#pragma unroll
        for (int j = 0; j < NT; ++j) {
            float yk = g_ypart[b][j][n] - c;
            float tt = s + yk;
            c = (tt - s) - yk;
            s = tt;
        }
        float v = g_dvec[b * Nn + n] * (s + c);
        out[OFF_S + b * Nn + n] = v;

        unsigned u  = __float_as_uint(v);
        unsigned up = (u & 0x80000000u) ? ~u : (u | 0x80000000u);
        unsigned kd = ~up;
        key[n] = ((unsigned long long)kd << 32) | (unsigned)n;
    }
    __syncthreads();

    for (int size = 2; size <= 4096; size <<= 1) {
        for (int stride = size >> 1; stride; stride >>= 1) {
#pragma unroll
            for (int q = 0; q < 2; ++q) {
                int t  = threadIdx.x + q * 1024;
                int lo = 2 * t - (t & (stride - 1));
                int hi = lo + stride;
                bool asc = (lo & size) == 0;
                unsigned long long a = key[lo], c = key[hi];
                if ((a > c) == asc) { key[lo] = c; key[hi] = a; }
            }
            __syncthreads();
        }
    }
    if (threadIdx.x < Kk)
        g_idx[b * Kk + threadIdx.x] = (int)(key[threadIdx.x] & 0xFFFFFFFFu);
}

// ------------------------------------------------------------------
// gather F_c, parallel over (b, k-chunk). grid (16, 8), 128 threads.
__global__ void k_gather(const float* __restrict__ X, float* __restrict__ out) {
    int b = blockIdx.y, kc = blockIdx.x, d = threadIdx.x;
#pragma unroll
    for (int q = 0; q < 16; ++q) {
        int k = kc * 16 + q;
        int n = g_idx[b * Kk + k];
        out[OFF_FC + ((size_t)b * Kk + k) * Dd + d] = X[((size_t)b * Nn + n) * Dd + d];
    }
}

// means: grid B, 128 threads (= d)
__global__ void k_means(const float* __restrict__ X, float* __restrict__ out) {
    int b = blockIdx.x, d = threadIdx.x;
    float s = 0.f;
#pragma unroll 4
    for (int k = 0; k < Kk; ++k) {
        int n = g_idx[b * Kk + k];
        s += X[((size_t)b * Nn + n) * Dd + d];
    }
    out[OFF_FCM  + b * Dd + d] = s * (1.f / (float)Kk);
    out[OFF_FNCM + b * Dd + d] = (g_colsum[b * Dd + d] - s) * (1.f / (float)(Nn - Kk));
}

// ------------------------------------------------------------------
extern "C" void kernel_launch(void* const* d_in, const int* in_sizes, int n_in,
                              void* d_out, int out_size) {
    const float* X = (const float*)d_in[0];   // [8,4096,128] f32
    const float* W = (const float*)d_in[1];   // [1,128] f32
    float* out = (float*)d_out;

    dim3 gmp(32, Bb);
    k_meanpart<<<gmp, 128>>>(X);
    k_meanred<<<4, 256>>>();

    k_vary<<<Bb * Nn, 128>>>(X, W);

    dim3 gc(NTILES, Bb);
    k_corr<<<gc, 256>>>();

    k_rowred<<<128, 256>>>();

    k_spmv<<<gc, 256>>>();

    k_stopk<<<Bb, 1024>>>(out);

    dim3 gg(16, Bb);
    k_gather<<<gg, 128>>>(X, out);
    k_means<<<Bb, 128>>>(X, out);
}